// round 16
// baseline (speedup 1.0000x reference)
#include <cuda_runtime.h>
#include <cstdint>

#define HH 128
#define WW 128
#define CC 64
#define OO 64
#define BB 2
#define KK9 9
#define HWSZ (HH*WW)

typedef unsigned long long ull;

// ---------------- f32x2 packed helpers -----------------------------------------
__device__ __forceinline__ ull pack2(float a, float b) {
    ull r; asm("mov.b64 %0, {%1, %2};" : "=l"(r) : "f"(a), "f"(b)); return r;
}
__device__ __forceinline__ ull bcast2(float a) {
    ull r; asm("mov.b64 %0, {%1, %1};" : "=l"(r) : "f"(a)); return r;
}
__device__ __forceinline__ void ffma2(ull& d, ull a, ull b) {
    asm("fma.rn.f32x2 %0, %1, %2, %0;" : "+l"(d) : "l"(a), "l"(b));
}
__device__ __forceinline__ void fadd2(ull& d, ull a) {
    asm("add.rn.f32x2 %0, %0, %1;" : "+l"(d) : "l"(a));
}
__device__ __forceinline__ float lo2(ull v) { return __uint_as_float((unsigned)v); }
__device__ __forceinline__ float hi2(ull v) { return __uint_as_float((unsigned)(v >> 32)); }

// ---------------- scratch ------------------------------------------------------
__device__ float g_wt[KK9*CC*OO];    // main weight -> [k*64+c][o]

// ---------------- K0: main-weight reorder --------------------------------------
__global__ __launch_bounds__(256) void reorder_kernel(
    const float* __restrict__ wsrc)   // [64][64][3][3]
{
    int i = blockIdx.x * 256 + threadIdx.x;
    if (i < OO*CC*KK9) {
        int o = i / (CC*KK9);
        int r = i % (CC*KK9);
        int c = r / KK9;
        int k = r % KK9;
        g_wt[(k*CC + c)*OO + o] = wsrc[i];
    }
}

// ---------------- fused kernel --------------------------------------------------
// CTA = (b, h) full row, 512 threads.
// Phase A: offset conv (f32x2 SIMT) -> bilinear metadata in SMEM.
// Phase B: software-pipelined sample + GEMM over 9 taps with double-buffered
//          S tiles: gather LDGs of tap k+1 are issued in register groups and
//          covered by tap k's GEMM chunks.
//
// smem bytes (phase-aliased, total 109568):
//   A: wsh  [0, 64512)        offw weights [c][tap][28]
//      part [64512, 95232)    combine buffer 2*128*15 ull
//   B: sIdxS [0, 9216)        ushort4 per (pix,k)
//      sWgt  [9216, 27648)    float4 per (pix,k)
//      Wsh   [27648, 44032)   W tap tile [64c][64o] f32
//      S0    [44032, 76800)   S tile [64c][128p] f32
//      S1    [76800, 109568)  S tile (double buffer)
__global__ __launch_bounds__(512, 2) void fused_kernel(
    const float* __restrict__ x,
    const float* __restrict__ offw,   // [27][64][3][3]
    const float* __restrict__ offb,   // [27]
    const float* __restrict__ bias,   // [64]
    float* __restrict__ out)
{
    extern __shared__ float sm[];
    char*    smc   = (char*)sm;
    float*   wsh   = sm;
    ull*     part  = (ull*)(smc + 64512);
    ushort4* sIdxS = (ushort4*)smc;
    float4*  sWgtB = (float4*)(smc + 9216);
    float*   Wsh   = (float*)(smc + 27648);
    float*   S0    = (float*)(smc + 44032);
    float*   S1    = (float*)(smc + 76800);

    int b = blockIdx.x >> 7;
    int h = blockIdx.x & 127;
    int t = threadIdx.x;

    // ================= Phase A: offset conv =================
    {
        int w  = t & 127;
        int cq = t >> 7;

        for (int i = t; i < 27*CC*KK9; i += 512) {
            int j  = i / (CC*KK9);
            int ct = i % (CC*KK9);
            wsh[ct*28 + j] = offw[i];
        }
        __syncthreads();

        ull acc2[14];
        if (cq == 0) {
            #pragma unroll
            for (int i = 0; i < 13; i++) acc2[i] = pack2(offb[2*i], offb[2*i+1]);
            acc2[13] = pack2(offb[26], 0.f);
        } else {
            #pragma unroll
            for (int i = 0; i < 14; i++) acc2[i] = 0ull;
        }

        const float* xb = x + b*CC*HWSZ;
        int c0 = cq * 16;
        for (int ci = 0; ci < 16; ci++) {
            int c = c0 + ci;
            float xv[9];
            const float* xp = xb + c*HWSZ;
            #pragma unroll
            for (int ki = 0; ki < 3; ki++) {
                int y = h - 1 + ki;
                bool yok = ((unsigned)y < HH);
                #pragma unroll
                for (int kj = 0; kj < 3; kj++) {
                    int xx = w - 1 + kj;
                    bool ok = yok && ((unsigned)xx < WW);
                    xv[ki*3+kj] = ok ? __ldg(xp + y*WW + xx) : 0.f;
                }
            }
            const float* wc = wsh + c*KK9*28;
            #pragma unroll
            for (int tap = 0; tap < 9; tap++) {
                ull xb2 = bcast2(xv[tap]);
                const ulonglong2* wt2 = (const ulonglong2*)(wc + tap*28);
                #pragma unroll
                for (int j2 = 0; j2 < 7; j2++) {
                    ulonglong2 ww = wt2[j2];
                    ffma2(acc2[j2*2    ], xb2, ww.x);
                    ffma2(acc2[j2*2 + 1], xb2, ww.y);
                }
            }
        }

        // tree combine: (2,3) -> (0,1), then 1 -> 0
        if (cq >= 2) {
            ull* dst = part + (long)(cq - 2)*128*15 + w*15;
            #pragma unroll
            for (int i = 0; i < 14; i++) dst[i] = acc2[i];
        }
        __syncthreads();   // all wsh reads complete after this point
        if (cq < 2) {
            ull* src = part + (long)cq*128*15 + w*15;
            #pragma unroll
            for (int i = 0; i < 14; i++) fadd2(acc2[i], src[i]);
        }
        __syncthreads();
        if (cq == 1) {
            ull* dst = part + w*15;
            #pragma unroll
            for (int i = 0; i < 14; i++) dst[i] = acc2[i];
        }
        __syncthreads();

        if (cq == 0) {
            ull* src = part + w*15;
            #pragma unroll
            for (int i = 0; i < 14; i++) fadd2(acc2[i], src[i]);

            float acc[27];
            #pragma unroll
            for (int j = 0; j < 27; j++)
                acc[j] = (j & 1) ? hi2(acc2[j >> 1]) : lo2(acc2[j >> 1]);

            // bilinear epilogue -> SMEM metadata (aliases dead wsh region)
            #pragma unroll
            for (int k = 0; k < 9; k++) {
                int ki = k / 3, kj = k % 3;
                float py = (float)(h - 1 + ki) + acc[k];
                float px = (float)(w - 1 + kj) + acc[9+k];
                float m  = 1.f / (1.f + __expf(-acc[18+k]));
                float y0f = floorf(py), x0f = floorf(px);
                float wy = py - y0f, wx = px - x0f;
                int y0 = (int)y0f, x0 = (int)x0f;
                int y1 = y0 + 1,  x1 = x0 + 1;
                bool v0y = ((unsigned)y0 < HH), v1y = ((unsigned)y1 < HH);
                bool v0x = ((unsigned)x0 < WW), v1x = ((unsigned)x1 < WW);
                float w00 = (v0y && v0x) ? (1.f-wy)*(1.f-wx)*m : 0.f;
                float w01 = (v0y && v1x) ? (1.f-wy)*wx*m       : 0.f;
                float w10 = (v1y && v0x) ? wy*(1.f-wx)*m       : 0.f;
                float w11 = (v1y && v1x) ? wy*wx*m             : 0.f;
                int cy0 = min(max(y0,0),HH-1), cy1 = min(max(y1,0),HH-1);
                int cx0 = min(max(x0,0),WW-1), cx1 = min(max(x1,0),WW-1);
                sIdxS[w*KK9 + k] = make_ushort4(
                    (unsigned short)(cy0*WW+cx0), (unsigned short)(cy0*WW+cx1),
                    (unsigned short)(cy1*WW+cx0), (unsigned short)(cy1*WW+cx1));
                sWgtB[w*KK9 + k] = make_float4(w00, w01, w10, w11);
            }
        }
    }
    __syncthreads();   // metadata ready; phase A smem dead

    // ================= Phase B: pipelined sample + GEMM =================
    {
        int tx  = t & 15;    // GEMM: o-quad
        int ty  = t >> 4;    // GEMM: p-quad 0..31
        int p   = t & 127;   // sampling: pixel
        int cph = t >> 7;    // sampling: channel phase 0..3

        // bias folded into accumulator init (acc packed over pixel pairs)
        ull acc2[4][2];
        #pragma unroll
        for (int i = 0; i < 4; i++) {
            ull bv = bcast2(__ldg(&bias[tx*4 + i]));
            acc2[i][0] = bv; acc2[i][1] = bv;
        }

        const float* xb = x + b*CC*HWSZ;

        // prologue: sample tap 0 into S0
        {
            ushort4 id = sIdxS[p*KK9];
            float4  wv = sWgtB[p*KK9];
            #pragma unroll
            for (int j = 0; j < 16; j++) {
                int c = cph + j*4;
                const float* xp = xb + c*HWSZ;
                float s = wv.x*__ldg(xp+id.x) + wv.y*__ldg(xp+id.y)
                        + wv.z*__ldg(xp+id.z) + wv.w*__ldg(xp+id.w);
                S0[c*WW + p] = s;
            }
        }

        for (int k = 0; k < KK9; k++) {
            float* cur = (k & 1) ? S1 : S0;
            float* nxt = (k & 1) ? S0 : S1;

            // prefetch W tap k into regs (hot in L2/L1)
            const float4* gw = (const float4*)(g_wt + k*CC*OO);
            float4 wr0 = __ldg(gw + t);
            float4 wr1 = __ldg(gw + t + 512);

            __syncthreads();   // prev GEMM done: Wsh free, nxt S-buf free
            {
                float4* w4 = (float4*)Wsh;
                w4[t]       = wr0;
                w4[t + 512] = wr1;
            }
            __syncthreads();   // W ready; cur fully visible

            ushort4 id; float4 wv;
            if (k < 8) {
                id = sIdxS[p*KK9 + k + 1];
                wv = sWgtB[p*KK9 + k + 1];
            }

            #pragma unroll
            for (int g = 0; g < 4; g++) {
                // issue gather LDGs for next tap, group g (16 loads in flight)
                float gv[16];
                if (k < 8) {
                    #pragma unroll
                    for (int jj = 0; jj < 4; jj++) {
                        int c = cph + (g*4 + jj)*4;
                        const float* xp = xb + c*HWSZ;
                        gv[jj*4+0] = __ldg(xp + id.x);
                        gv[jj*4+1] = __ldg(xp + id.y);
                        gv[jj*4+2] = __ldg(xp + id.z);
                        gv[jj*4+3] = __ldg(xp + id.w);
                    }
                }

                // GEMM chunk: 16 c-steps (covers the gather latency)
                #pragma unroll 4
                for (int c = g*16; c < g*16 + 16; c++) {
                    float4     wr = *(const float4*)&Wsh[c*OO + tx*4];
                    ulonglong2 sv = *(const ulonglong2*)&cur[c*WW + ty*4];
                    ull b0 = bcast2(wr.x);
                    ull b1 = bcast2(wr.y);
                    ull b2 = bcast2(wr.z);
                    ull b3 = bcast2(wr.w);
                    ffma2(acc2[0][0], b0, sv.x); ffma2(acc2[0][1], b0, sv.y);
                    ffma2(acc2[1][0], b1, sv.x); ffma2(acc2[1][1], b1, sv.y);
                    ffma2(acc2[2][0], b2, sv.x); ffma2(acc2[2][1], b2, sv.y);
                    ffma2(acc2[3][0], b3, sv.x); ffma2(acc2[3][1], b3, sv.y);
                }

                // combine + store samples into next buffer
                if (k < 8) {
                    #pragma unroll
                    for (int jj = 0; jj < 4; jj++) {
                        int c = cph + (g*4 + jj)*4;
                        float s = wv.x*gv[jj*4+0] + wv.y*gv[jj*4+1]
                                + wv.z*gv[jj*4+2] + wv.w*gv[jj*4+3];
                        nxt[c*WW + p] = s;
                    }
                }
            }
        }

        // write out directly (bias already in acc)
        #pragma unroll
        for (int i = 0; i < 4; i++) {
            int o = tx*4 + i;
            float4 r = make_float4(lo2(acc2[i][0]), hi2(acc2[i][0]),
                                   lo2(acc2[i][1]), hi2(acc2[i][1]));
            *(float4*)&out[(long)(b*OO + o)*HWSZ + h*WW + ty*4] = r;
        }
    }
}

// ---------------- launch --------------------------------------------------------
extern "C" void kernel_launch(void* const* d_in, const int* in_sizes, int n_in,
                              void* d_out, int out_size)
{
    // identify inputs by element count (robust to ordering)
    const float *x = 0, *wt = 0, *bs = 0, *ow = 0, *ob = 0;
    for (int i = 0; i < n_in; i++) {
        switch (in_sizes[i]) {
            case BB*CC*HWSZ:   x  = (const float*)d_in[i]; break; // 2097152
            case OO*CC*KK9:    wt = (const float*)d_in[i]; break; // 36864
            case OO:           bs = (const float*)d_in[i]; break; // 64
            case 27*CC*KK9:    ow = (const float*)d_in[i]; break; // 15552
            case 27:           ob = (const float*)d_in[i]; break; // 27
        }
    }
    float* out = (float*)d_out;

    const int smemF = 109568;   // max(phase A 95232, phase B 109568)
    cudaFuncSetAttribute(fused_kernel, cudaFuncAttributeMaxDynamicSharedMemorySize, smemF);

    reorder_kernel<<<(OO*CC*KK9 + 255)/256, 256>>>(wt);
    fused_kernel<<<BB*HH, 512, smemF>>>(x, ow, ob, bs, out);
}